// round 7
// baseline (speedup 1.0000x reference)
#include <cuda_runtime.h>
#include <math.h>

#define T1V 257
#define BATCH 512
#define SDV 128
#define ADV 32
#define HSV 512
#define SFV 256
#define R2 131072    // 256*512 rows
#define RALL 131584  // 257*512 rows

// ---------------- scratch (__device__ globals; no runtime allocation) ----------------
__device__ float g_feats [(size_t)T1V * BATCH * HSV];     // 257x512x512
__device__ float g_xw    [(size_t)RALL * 1024];           // feats@Wih0^T + bih0
__device__ float g_outs  [(size_t)T1V * BATCH * SFV];     // h1 history (257 slots)
__device__ float g_h0hist[(size_t)(T1V + 1) * BATCH * SFV]; // h0 history, slot0 = zeros
__device__ float g_pred  [(size_t)256 * BATCH * SFV];
__device__ float g_hidA  [(size_t)R2 * HSV];
__device__ float g_hidB  [(size_t)R2 * HSV];
__device__ float g_c0    [BATCH * SFV];
__device__ float g_c1    [BATCH * SFV];
__device__ float g_pfl   [2048];
__device__ float g_pil   [512];

__device__ __forceinline__ float sigmoidf_(float x) { return 1.0f / (1.0f + expf(-x)); }

// ---------------- init: zero c0,c1 and h0hist slot 0 ----------------
__global__ void init_kernel() {
    int i = blockIdx.x * blockDim.x + threadIdx.x;  // 131072
    g_c0[i] = 0.f; g_c1[i] = 0.f;
    g_h0hist[i] = 0.f;
}

// ---------------- merged LSTM step: L0(s0) and L1(s1) in one launch --------------
// grid 512 CTAs: blk<256 -> layer0 tile, else layer1 tile. Tile 32 batch x 64 gatecols.
// 256 threads = 4 kgroups x 64. Microtile 4 batch x 8 gatecols.
// smem floats: per kgroup [2 bufs][ab 16x36=576 | wb 16x68=1088] = 3328; x4 = 13312
//              red 32x68 = 2176 @13312 ; msk 32 @15488 ; total 15520 (62 KB)
__global__ __launch_bounds__(256, 2) void lstm_merged(
    int s0, int s1,
    float* __restrict__ h0hist,          // (258)*131072
    const float* __restrict__ xw,
    float* __restrict__ outs,            // 257*131072
    float* __restrict__ c0, float* __restrict__ c1,
    const float* __restrict__ Whh0, const float* __restrict__ bhh0,
    const float* __restrict__ Wih1, const float* __restrict__ Whh1,
    const float* __restrict__ bih1, const float* __restrict__ bhh1,
    const int* __restrict__ dones,
    float* __restrict__ hid)
{
    extern __shared__ float sh[];
    float* red = sh + 13312;
    float* msk = sh + 15488;

    const bool isL0 = (blockIdx.x < 256);
    const int step = isL0 ? s0 : s1;
    if (step < 0) return;
    const int blk = isL0 ? blockIdx.x : (blockIdx.x - 256);
    const int bt = blk >> 4, gt = blk & 15;
    const int b0 = bt << 5, u0 = gt << 4;
    const int tid = threadIdx.x;
    const int kg = tid >> 6, kt = tid & 63;

    const int* done = dones + (size_t)step * BATCH;
    if (tid < 32) msk[tid] = 1.f - (float)done[b0 + tid];

    // kgroup source config
    const float* As; const float* W; int koff, nch; bool um;
    if (isL0) {
        As = h0hist + (size_t)s0 * 131072;
        W = Whh0; koff = kg << 6; um = true; nch = 4;
    } else {
        const float* h0in = h0hist + (size_t)(s1 + 1) * 131072;
        const float* h1in = (s1 == 0) ? h0hist /*slot0 zeros*/ : outs + (size_t)(s1 - 1) * 131072;
        As = (kg < 2) ? h0in : h1in;
        W  = (kg < 2) ? Wih1 : Whh1;
        koff = (kg & 1) << 7; um = (kg >= 2); nch = 8;
    }

    const int br = kt & 31;           // batch row this thread loads
    const int ka = (kt >> 5) << 3;    // k-sub offset for A (0/8)
    const int kw = (kt >> 4) << 2;    // k-sub offset for W (0,4,8,12)
    const int wu = kt & 15;           // unit for W rows
    const float* Arow = As + (size_t)(b0 + br) * SFV + koff + ka;
    const float* Wr[4];
#pragma unroll
    for (int j = 0; j < 4; j++)
        Wr[j] = W + (size_t)((j << 8) + u0 + wu) * SFV + koff + kw;

    float* myb = sh + kg * 3328;      // [buf][ab 576 | wb 1088]

    float acc[4][8];
#pragma unroll
    for (int i = 0; i < 4; i++)
#pragma unroll
        for (int j = 0; j < 8; j++) acc[i][j] = 0.f;

    float4 av0, av1, wv[4];
    const int mi = kt >> 3, ni = kt & 7;

#define LDCH(ch) { int kk = (ch) << 4; \
    av0 = *(const float4*)(Arow + kk); av1 = *(const float4*)(Arow + kk + 4); \
    wv[0] = *(const float4*)(Wr[0] + kk); wv[1] = *(const float4*)(Wr[1] + kk); \
    wv[2] = *(const float4*)(Wr[2] + kk); wv[3] = *(const float4*)(Wr[3] + kk); }

#define STCH(buf) { float* ab = myb + (buf) * 1664; float* wb = ab + 576; \
    float m_ = um ? msk[br] : 1.f; \
    ab[(ka + 0) * 36 + br] = av0.x * m_; ab[(ka + 1) * 36 + br] = av0.y * m_; \
    ab[(ka + 2) * 36 + br] = av0.z * m_; ab[(ka + 3) * 36 + br] = av0.w * m_; \
    ab[(ka + 4) * 36 + br] = av1.x * m_; ab[(ka + 5) * 36 + br] = av1.y * m_; \
    ab[(ka + 6) * 36 + br] = av1.z * m_; ab[(ka + 7) * 36 + br] = av1.w * m_; \
    _Pragma("unroll") \
    for (int j = 0; j < 4; j++) { \
        int gc = (wu << 2) + j; \
        wb[(kw + 0) * 68 + gc] = wv[j].x; wb[(kw + 1) * 68 + gc] = wv[j].y; \
        wb[(kw + 2) * 68 + gc] = wv[j].z; wb[(kw + 3) * 68 + gc] = wv[j].w; } }

#define CPCH(buf) { const float* ab = myb + (buf) * 1664 + (mi << 2); \
    const float* wb = myb + (buf) * 1664 + 576 + (ni << 3); \
    _Pragma("unroll") \
    for (int k = 0; k < 16; k++) { \
        float4 a4 = *(const float4*)(ab + k * 36); \
        float4 w0 = *(const float4*)(wb + k * 68); \
        float4 w1 = *(const float4*)(wb + k * 68 + 4); \
        float aa[4] = {a4.x, a4.y, a4.z, a4.w}; \
        float ww[8] = {w0.x, w0.y, w0.z, w0.w, w1.x, w1.y, w1.z, w1.w}; \
        _Pragma("unroll") \
        for (int i = 0; i < 4; i++) \
        _Pragma("unroll") \
        for (int j = 0; j < 8; j++) acc[i][j] += aa[i] * ww[j]; } }

    LDCH(0);
    __syncthreads();   // msk visible before STCH
    STCH(0);
    __syncthreads();
    for (int ch = 0; ch < nch; ch++) {
        if (ch + 1 < nch) {
            LDCH(ch + 1);
            CPCH(ch & 1);
            STCH((ch + 1) & 1);
            __syncthreads();
        } else {
            CPCH(ch & 1);
        }
    }

    // split-K reduce: kg1..3 -> kg0 via red (32x68), 3 rounds
#pragma unroll
    for (int g = 1; g < 4; g++) {
        __syncthreads();
        if (kg == g) {
#pragma unroll
            for (int i = 0; i < 4; i++) {
                *(float4*)(red + ((mi << 2) + i) * 68 + (ni << 3))     = make_float4(acc[i][0], acc[i][1], acc[i][2], acc[i][3]);
                *(float4*)(red + ((mi << 2) + i) * 68 + (ni << 3) + 4) = make_float4(acc[i][4], acc[i][5], acc[i][6], acc[i][7]);
            }
        }
        __syncthreads();
        if (kg == 0) {
#pragma unroll
            for (int i = 0; i < 4; i++) {
                float4 r0 = *(const float4*)(red + ((mi << 2) + i) * 68 + (ni << 3));
                float4 r1 = *(const float4*)(red + ((mi << 2) + i) * 68 + (ni << 3) + 4);
                acc[i][0] += r0.x; acc[i][1] += r0.y; acc[i][2] += r0.z; acc[i][3] += r0.w;
                acc[i][4] += r1.x; acc[i][5] += r1.y; acc[i][6] += r1.z; acc[i][7] += r1.w;
            }
        }
    }
    __syncthreads();
    if (kg == 0) {
#pragma unroll
        for (int i = 0; i < 4; i++) {
            *(float4*)(red + ((mi << 2) + i) * 68 + (ni << 3))     = make_float4(acc[i][0], acc[i][1], acc[i][2], acc[i][3]);
            *(float4*)(red + ((mi << 2) + i) * 68 + (ni << 3) + 4) = make_float4(acc[i][4], acc[i][5], acc[i][6], acc[i][7]);
        }
    }
    __syncthreads();

    // epilogue: 512 cells (32b x 16u), 2 per thread
    const int ul = tid & 15;
    const int u = u0 + ul;
    float* cst = isL0 ? c0 : c1;
    float* hw  = isL0 ? (h0hist + (size_t)(s0 + 1) * 131072)
                      : (outs + (size_t)s1 * 131072);
    float* hh = nullptr; float* hc = nullptr;
    if (isL0 && s0 == 256) { hh = hid;          hc = hid + 262144; }
    if (!isL0 && s1 == 256) { hh = hid + 131072; hc = hid + 393216; }
    float bb[4];
#pragma unroll
    for (int g = 0; g < 4; g++)
        bb[g] = isL0 ? bhh0[(g << 8) + u] : (bih1[(g << 8) + u] + bhh1[(g << 8) + u]);

#pragma unroll
    for (int q = 0; q < 2; q++) {
        int bl = (q << 4) + (tid >> 4);
        int b = b0 + bl;
        float4 pre = *(const float4*)(red + bl * 68 + (ul << 2));
        float x0 = 0.f, x1 = 0.f, x2 = 0.f, x3 = 0.f;
        if (isL0) {
            const float* xr = xw + (size_t)s0 * 524288 + (size_t)b * 1024 + u;
            x0 = xr[0]; x1 = xr[256]; x2 = xr[512]; x3 = xr[768];
        }
        float ig = sigmoidf_(pre.x + bb[0] + x0);
        float fg = sigmoidf_(pre.y + bb[1] + x1);
        float gg = tanhf(pre.z + bb[2] + x2);
        float og = sigmoidf_(pre.w + bb[3] + x3);
        float m = msk[bl];
        int idx = b * SFV + u;
        float c2 = fg * (cst[idx] * m) + ig * gg;
        float h2 = og * tanhf(c2);
        cst[idx] = c2;
        hw[idx] = h2;
        if (hh) { hh[idx] = h2; hc[idx] = c2; }
    }
#undef LDCH
#undef STCH
#undef CPCH
}

// ---------------- generic SGEMM: C = act(A @ W^T + bias) ----------------
#define KC 16
template <int ACT>
__global__ __launch_bounds__(256) void gemm_kernel(
    const float* __restrict__ A1, int K1,
    const float* __restrict__ A2,
    const float* __restrict__ W,
    const float* __restrict__ bias,
    float* __restrict__ C,
    int M, int N, int K)
{
    __shared__ float as_[KC][132];
    __shared__ float bs_[KC][132];
    const int m0 = blockIdx.x * 128;
    const int n0 = blockIdx.y * 128;
    const int tid = threadIdx.x;
    const int mi = tid >> 4;
    const int ni = tid & 15;
    const int lrow = tid >> 2;
    const int lk = (tid & 3) * 4;

    float acc[8][8];
#pragma unroll
    for (int i = 0; i < 8; i++)
#pragma unroll
        for (int j = 0; j < 8; j++) acc[i][j] = 0.f;

    for (int kc = 0; kc < K; kc += KC) {
        const float* Asrc;
        int Ak, koff;
        if (kc < K1) { Asrc = A1; Ak = K1; koff = kc; }
        else         { Asrc = A2; Ak = K - K1; koff = kc - K1; }
#pragma unroll
        for (int r = 0; r < 2; r++) {
            int row = lrow + r * 64;
            float4 v = *(const float4*)(Asrc + (size_t)(m0 + row) * Ak + koff + lk);
            as_[lk + 0][row] = v.x; as_[lk + 1][row] = v.y;
            as_[lk + 2][row] = v.z; as_[lk + 3][row] = v.w;
            float4 w = *(const float4*)(W + (size_t)(n0 + row) * K + kc + lk);
            bs_[lk + 0][row] = w.x; bs_[lk + 1][row] = w.y;
            bs_[lk + 2][row] = w.z; bs_[lk + 3][row] = w.w;
        }
        __syncthreads();
#pragma unroll
        for (int k = 0; k < KC; k++) {
            float4 a0 = *(const float4*)&as_[k][mi * 8];
            float4 a1 = *(const float4*)&as_[k][mi * 8 + 4];
            float a[8] = {a0.x, a0.y, a0.z, a0.w, a1.x, a1.y, a1.z, a1.w};
            float b[8];
#pragma unroll
            for (int j = 0; j < 8; j++) b[j] = bs_[k][ni + j * 16];
#pragma unroll
            for (int i = 0; i < 8; i++)
#pragma unroll
                for (int j = 0; j < 8; j++) acc[i][j] += a[i] * b[j];
        }
        __syncthreads();
    }
#pragma unroll
    for (int i = 0; i < 8; i++) {
        int row = m0 + mi * 8 + i;
#pragma unroll
        for (int j = 0; j < 8; j++) {
            int col = n0 + ni + j * 16;
            float v = acc[i][j] + bias[col];
            if (ACT == 1) v = fmaxf(v, 0.f);
            C[(size_t)row * N + col] = v;
        }
    }
}

// ---------------- forward loss + intrinsic reward ----------------
__global__ void floss_kernel(const float* __restrict__ pred, const float* __restrict__ outs,
                             float* __restrict__ intr, float* __restrict__ pfl)
{
    const int w = threadIdx.x >> 5, lane = threadIdx.x & 31;
    const int r0 = blockIdx.x * 64;
    __shared__ float sred[8];
    float wacc = 0.f;
    for (int p = 0; p < 8; p++) {
        int r = r0 + p * 8 + w;
        const float4* pp = (const float4*)(pred + (size_t)r * SFV) + lane * 2;
        const float4* np = (const float4*)(outs + (size_t)(r + BATCH) * SFV) + lane * 2;
        float4 p0 = pp[0], p1 = pp[1], n0 = np[0], n1 = np[1];
        float d0 = p0.x - n0.x, d1 = p0.y - n0.y, d2 = p0.z - n0.z, d3 = p0.w - n0.w;
        float d4 = p1.x - n1.x, d5 = p1.y - n1.y, d6 = p1.z - n1.z, d7 = p1.w - n1.w;
        float s = d0 * d0 + d1 * d1 + d2 * d2 + d3 * d3 + d4 * d4 + d5 * d5 + d6 * d6 + d7 * d7;
#pragma unroll
        for (int o = 16; o; o >>= 1) s += __shfl_xor_sync(0xffffffffu, s, o);
        if (lane == 0) { intr[r] = s; wacc += s; }
    }
    if (lane == 0) sred[w] = wacc;
    __syncthreads();
    if (threadIdx.x == 0) {
        float t = 0.f;
        for (int i = 0; i < 8; i++) t += sred[i];
        pfl[blockIdx.x] = t;
    }
}

// ---------------- inverse head: mu/std + NLL partials ----------------
__global__ void inv_kernel(const float* __restrict__ hm, const float* __restrict__ hs,
                           const float* __restrict__ Wm2, const float* __restrict__ bm2,
                           const float* __restrict__ Ws2, const float* __restrict__ bs2,
                           const float* __restrict__ act, float* __restrict__ pil)
{
    extern __shared__ float sh[];
    float* wm = sh;
    float* ws2s = sh + 16384;
    float* bm = sh + 32768;
    float* bs = sh + 32800;
    float* red = sh + 32832;
    const int tid = threadIdx.x;
    for (int idx = tid; idx < 16384; idx += 256) {
        int d = idx & 31, k = idx >> 5;
        wm[idx] = Wm2[(size_t)d * HSV + k];
        ws2s[idx] = Ws2[(size_t)d * HSV + k];
    }
    if (tid < 32) { bm[tid] = bm2[tid]; bs[tid] = bs2[tid]; }
    __syncthreads();

    const int w = tid >> 5, lane = tid & 31;
    const int r0 = blockIdx.x * 256;
    float ilacc = 0.f;
    for (int p = 0; p < 32; p++) {
        int r = r0 + p * 8 + w;
        const float4* h4m = (const float4*)(hm + (size_t)r * HSV);
        const float4* h4s = (const float4*)(hs + (size_t)r * HSV);
        float am = 0.f, as2 = 0.f;
#pragma unroll 4
        for (int k4 = 0; k4 < 128; k4++) {
            float4 a = h4m[k4];
            float4 b = h4s[k4];
            int kb = k4 * 128 + lane;
            am  += a.x * wm[kb] + a.y * wm[kb + 32] + a.z * wm[kb + 64] + a.w * wm[kb + 96];
            as2 += b.x * ws2s[kb] + b.y * ws2s[kb + 32] + b.z * ws2s[kb + 64] + b.w * ws2s[kb + 96];
        }
        float mu = tanhf(am + bm[lane]);
        float sv = as2 + bs[lane];
        float sd = fmaxf(sv, 0.f) + log1pf(expf(-fabsf(sv)));
        float a_ = act[(size_t)r * ADV + lane];
        float z = (a_ - mu) / sd;
        ilacc += 0.5f * z * z + logf(sd) + 0.91893853320467274f;
    }
#pragma unroll
    for (int o = 16; o; o >>= 1) ilacc += __shfl_xor_sync(0xffffffffu, ilacc, o);
    if (lane == 0) red[w] = ilacc;
    __syncthreads();
    if (tid == 0) {
        float t = 0.f;
        for (int i = 0; i < 8; i++) t += red[i];
        pil[blockIdx.x] = t;
    }
}

// ---------------- final scalar reduce ----------------
__global__ void final_reduce_kernel(const float* __restrict__ pfl, const float* __restrict__ pil,
                                    float* __restrict__ out)
{
    __shared__ float s1[256], s2[256];
    int tid = threadIdx.x;
    float a = 0.f, b = 0.f;
    for (int i = tid; i < 2048; i += 256) a += pfl[i];
    for (int i = tid; i < 512; i += 256) b += pil[i];
    s1[tid] = a; s2[tid] = b;
    __syncthreads();
    for (int st = 128; st; st >>= 1) {
        if (tid < st) { s1[tid] += s1[tid + st]; s2[tid] += s2[tid + st]; }
        __syncthreads();
    }
    if (tid == 0) {
        out[0] = s1[0] / 33554432.f;
        out[1] = s2[0] / 4194304.f;
    }
}

// ---------------- host orchestration ----------------
extern "C" void kernel_launch(void* const* d_in, const int* in_sizes, int n_in,
                              void* d_out, int out_size)
{
    (void)in_sizes; (void)n_in; (void)out_size;
    const float* states = (const float*)d_in[0];
    const float* action = (const float*)d_in[1];
    const int*   dones  = (const int*)d_in[2];
    const float* Wfe = (const float*)d_in[3];
    const float* bfe = (const float*)d_in[4];
    const float* Wih0 = (const float*)d_in[5];
    const float* Whh0 = (const float*)d_in[6];
    const float* bih0 = (const float*)d_in[7];
    const float* bhh0 = (const float*)d_in[8];
    const float* Wih1 = (const float*)d_in[9];
    const float* Whh1 = (const float*)d_in[10];
    const float* bih1 = (const float*)d_in[11];
    const float* bhh1 = (const float*)d_in[12];
    const float* Wf1 = (const float*)d_in[13];
    const float* bf1 = (const float*)d_in[14];
    const float* Wf2 = (const float*)d_in[15];
    const float* bf2 = (const float*)d_in[16];
    const float* Wm1 = (const float*)d_in[17];
    const float* bm1 = (const float*)d_in[18];
    const float* Wm2 = (const float*)d_in[19];
    const float* bm2 = (const float*)d_in[20];
    const float* Ws1 = (const float*)d_in[21];
    const float* bs1 = (const float*)d_in[22];
    const float* Ws2 = (const float*)d_in[23];
    const float* bs2 = (const float*)d_in[24];
    float* out = (float*)d_out;

    float *feats, *xw, *outs, *h0hist, *pred, *hidA, *hidB, *c0, *c1, *pfl, *pil;
    cudaGetSymbolAddress((void**)&feats, g_feats);
    cudaGetSymbolAddress((void**)&xw, g_xw);
    cudaGetSymbolAddress((void**)&outs, g_outs);
    cudaGetSymbolAddress((void**)&h0hist, g_h0hist);
    cudaGetSymbolAddress((void**)&pred, g_pred);
    cudaGetSymbolAddress((void**)&hidA, g_hidA);
    cudaGetSymbolAddress((void**)&hidB, g_hidB);
    cudaGetSymbolAddress((void**)&c0, g_c0);
    cudaGetSymbolAddress((void**)&c1, g_c1);
    cudaGetSymbolAddress((void**)&pfl, g_pfl);
    cudaGetSymbolAddress((void**)&pil, g_pil);

    const int msSmem = 15520 * 4;
    cudaFuncSetAttribute(inv_kernel, cudaFuncAttributeMaxDynamicSharedMemorySize, 32840 * 4);
    cudaFuncSetAttribute(lstm_merged, cudaFuncAttributeMaxDynamicSharedMemorySize, msSmem);

    // init recurrent state
    init_kernel<<<256, 512>>>();

    // feature encoder: feats = relu(states @ Wfe^T + bfe)
    gemm_kernel<1><<<dim3(RALL / 128, HSV / 128), 256>>>(
        states, SDV, nullptr, Wfe, bfe, feats, RALL, HSV, SDV);

    // hoisted layer-0 input gates: xw = feats @ Wih0^T + bih0
    gemm_kernel<0><<<dim3(RALL / 128, 1024 / 128), 256>>>(
        feats, HSV, nullptr, Wih0, bih0, xw, RALL, 1024, HSV);

    // LSTM scan: one merged launch per step
    float* hid = out + 2 + 131072;
    lstm_merged<<<512, 256, msSmem>>>(0, -1, h0hist, xw, outs, c0, c1,
        Whh0, bhh0, Wih1, Whh1, bih1, bhh1, dones, hid);
    for (int t = 0; t < 256; t++) {
        lstm_merged<<<512, 256, msSmem>>>(t + 1, t, h0hist, xw, outs, c0, c1,
            Whh0, bhh0, Wih1, Whh1, bih1, bhh1, dones, hid);
    }
    lstm_merged<<<512, 256, msSmem>>>(-1, 256, h0hist, xw, outs, c0, c1,
        Whh0, bhh0, Wih1, Whh1, bih1, bhh1, dones, hid);

    // forward model
    gemm_kernel<1><<<dim3(R2 / 128, HSV / 128), 256>>>(
        outs, SFV, action, Wf1, bf1, hidA, R2, HSV, SFV + ADV);
    gemm_kernel<0><<<dim3(R2 / 128, SFV / 128), 256>>>(
        hidA, HSV, nullptr, Wf2, bf2, pred, R2, SFV, HSV);

    // forward loss + intrinsic reward
    floss_kernel<<<2048, 256>>>(pred, outs, out + 2, pfl);

    // inverse model hiddens
    gemm_kernel<1><<<dim3(R2 / 128, HSV / 128), 256>>>(
        outs, SFV, pred, Wm1, bm1, hidA, R2, HSV, 2 * SFV);
    gemm_kernel<1><<<dim3(R2 / 128, HSV / 128), 256>>>(
        outs, SFV, pred, Ws1, bs1, hidB, R2, HSV, 2 * SFV);

    // mu/std + inverse-loss partials
    inv_kernel<<<512, 256, 32840 * 4>>>(hidA, hidB, Wm2, bm2, Ws2, bs2, action, pil);

    // scalars
    final_reduce_kernel<<<1, 256>>>(pfl, pil, out);
}